// round 2
// baseline (speedup 1.0000x reference)
#include <cuda_runtime.h>
#include <cstdint>

// Scratch (no allocations allowed — __device__ globals)
static __device__ float g_T[16 * 16 * 16 * 16 * 16];   // 4 MB  [i][j][m][n][s]
static __device__ float g_W[4096 * 4096];              // 64 MB [row=ijk][col=mno], tf32-rounded

__device__ __forceinline__ float to_tf32(float x) {
    float y;
    asm("cvt.rna.tf32.f32 %0, %1;" : "=f"(y) : "f"(x));
    return y;
}

// ---------------------------------------------------------------------------
// Stage 1: T[i,j,m,n,s] = sum_r first[i,r,m] * middle[j,r,s,n]
// ---------------------------------------------------------------------------
__global__ void mpo_stage1(const float* __restrict__ first,
                           const float* __restrict__ middle) {
    int id = blockIdx.x * 256 + threadIdx.x;            // 1,048,576 total
    int s = id & 15;
    int n = (id >> 4) & 15;
    int m = (id >> 8) & 15;
    int j = (id >> 12) & 15;
    int i = id >> 16;
    float acc = 0.f;
#pragma unroll
    for (int r = 0; r < 16; r++)
        acc += first[(i * 16 + r) * 16 + m] *
               middle[((j * 16 + r) * 16 + s) * 16 + n];
    g_T[id] = acc;
}

// ---------------------------------------------------------------------------
// Stage 2: W[(i,j,k), (m,n,o)] = sum_s T[i,j,m,n,s] * last[k,s,o]
// One block = (row=ijk, m); 256 threads cover (n,o). Result tf32-rounded.
// ---------------------------------------------------------------------------
__global__ void mpo_stage2(const float* __restrict__ last) {
    __shared__ float Ts[256];   // [n][s]
    __shared__ float Ls[256];   // [s][o]
    int row = blockIdx.x;       // 0..4095  (i,j,k)
    int m   = blockIdx.y;       // 0..15
    int i = row >> 8, j = (row >> 4) & 15, k = row & 15;
    int t = threadIdx.x;
    Ts[t] = g_T[(((i * 16 + j) * 16 + m) * 16 + (t >> 4)) * 16 + (t & 15)];
    Ls[t] = last[(k * 16 + (t >> 4)) * 16 + (t & 15)];
    __syncthreads();
    int n = t >> 4, o = t & 15;
    float acc = 0.f;
#pragma unroll
    for (int s = 0; s < 16; s++)
        acc += Ts[n * 16 + s] * Ls[s * 16 + o];
    g_W[row * 4096 + m * 256 + n * 16 + o] = to_tf32(acc);
}

// ---------------------------------------------------------------------------
// Stage 3: out = X(2048x4096) @ W(4096x4096) + bias, tf32 mma.sync
// CTA tile 128x128, BK=32, double-buffered smem, 8 warps (2M x 4N),
// warp tile 64x32, m16n8k8.tf32.
// Smem: As [m][36]  (stride 36 == 4 mod 32  -> conflict-free A frags)
//       Bs [k][136] (stride 136 == 8 mod 32 -> conflict-free B frags)
// Both strides keep rows 16B-aligned for STS.128.
// ---------------------------------------------------------------------------
#define ASTR 36
#define BSTR 136
#define ABUF (128 * ASTR)            // 4608 floats
#define BBUF (32 * BSTR)             // 4352 floats
#define TBUF (ABUF + BBUF)           // 8960 floats per stage
#define SMEM_BYTES (2 * TBUF * 4)    // 71680 B

__global__ void __launch_bounds__(256, 1)
mpo_gemm(const float* __restrict__ X, const float* __restrict__ bias,
         float* __restrict__ out) {
    extern __shared__ float sm[];
    const int tid  = threadIdx.x;
    const int lane = tid & 31;
    const int warp = tid >> 5;
    const int gid  = lane >> 2;      // 0..7
    const int tig  = lane & 3;       // 0..3
    const int warpM = warp & 1;      // 2 warps along M
    const int warpN = warp >> 1;     // 4 warps along N
    const int bM = blockIdx.y << 7;
    const int bN = blockIdx.x << 7;

    // global-load coordinates (float4 granularity)
    int a_row[4], a_kc[4], b_row[4], b_nc[4];
#pragma unroll
    for (int i = 0; i < 4; i++) {
        int f4 = tid + i * 256;
        a_row[i] = f4 >> 3;          // 0..127
        a_kc[i]  = (f4 & 7) << 2;    // 0..28
        b_row[i] = f4 >> 5;          // 0..31
        b_nc[i]  = (f4 & 31) << 2;   // 0..124
    }

    float acc[4][4][4];
#pragma unroll
    for (int mt = 0; mt < 4; mt++)
#pragma unroll
        for (int nt = 0; nt < 4; nt++)
#pragma unroll
            for (int q = 0; q < 4; q++) acc[mt][nt][q] = 0.f;

    float4 ar[4], br[4];

    // prologue: load k-tile 0
#pragma unroll
    for (int i = 0; i < 4; i++) {
        ar[i] = *(const float4*)(X + (size_t)(bM + a_row[i]) * 4096 + a_kc[i]);
        br[i] = *(const float4*)(g_W + (size_t)b_row[i] * 4096 + bN + b_nc[i]);
    }
    {
        float* As = sm;
        float* Bs = sm + ABUF;
#pragma unroll
        for (int i = 0; i < 4; i++) {
            float4 v;
            v.x = to_tf32(ar[i].x); v.y = to_tf32(ar[i].y);
            v.z = to_tf32(ar[i].z); v.w = to_tf32(ar[i].w);
            *(float4*)(As + a_row[i] * ASTR + a_kc[i]) = v;
            *(float4*)(Bs + b_row[i] * BSTR + b_nc[i]) = br[i];   // W already tf32
        }
    }
    __syncthreads();

    int buf = 0;
    const int mBase = warpM * 64 + gid;
    const int nBase = warpN * 32 + gid;

    for (int kt = 0; kt < 128; kt++) {
        // prefetch next k-tile into registers (latency hidden by compute)
        if (kt < 127) {
            const int kofs = (kt + 1) * 32;
#pragma unroll
            for (int i = 0; i < 4; i++) {
                ar[i] = *(const float4*)(X + (size_t)(bM + a_row[i]) * 4096 + kofs + a_kc[i]);
                br[i] = *(const float4*)(g_W + (size_t)(kofs + b_row[i]) * 4096 + bN + b_nc[i]);
            }
        }

        // compute on current buffer
        {
            const float* As = sm + buf * TBUF;
            const float* Bs = As + ABUF;
#pragma unroll
            for (int ks = 0; ks < 4; ks++) {
                const int k0 = ks * 8 + tig;
                uint32_t a[4][4], b[4][2];
#pragma unroll
                for (int mt = 0; mt < 4; mt++) {
                    const float* p = As + (mBase + mt * 16) * ASTR + k0;
                    a[mt][0] = __float_as_uint(p[0]);
                    a[mt][1] = __float_as_uint(p[8 * ASTR]);
                    a[mt][2] = __float_as_uint(p[4]);
                    a[mt][3] = __float_as_uint(p[8 * ASTR + 4]);
                }
#pragma unroll
                for (int nt = 0; nt < 4; nt++) {
                    const float* p = Bs + k0 * BSTR + nBase + nt * 8;
                    b[nt][0] = __float_as_uint(p[0]);
                    b[nt][1] = __float_as_uint(p[4 * BSTR]);
                }
#pragma unroll
                for (int mt = 0; mt < 4; mt++)
#pragma unroll
                    for (int nt = 0; nt < 4; nt++) {
                        asm volatile(
                            "mma.sync.aligned.m16n8k8.row.col.f32.tf32.tf32.f32 "
                            "{%0,%1,%2,%3}, {%4,%5,%6,%7}, {%8,%9}, {%0,%1,%2,%3};\n"
                            : "+f"(acc[mt][nt][0]), "+f"(acc[mt][nt][1]),
                              "+f"(acc[mt][nt][2]), "+f"(acc[mt][nt][3])
                            : "r"(a[mt][0]), "r"(a[mt][1]),
                              "r"(a[mt][2]), "r"(a[mt][3]),
                              "r"(b[nt][0]), "r"(b[nt][1]));
                    }
            }
        }

        // stage next tile into the other buffer
        if (kt < 127) {
            float* As = sm + (buf ^ 1) * TBUF;
            float* Bs = As + ABUF;
#pragma unroll
            for (int i = 0; i < 4; i++) {
                float4 v;
                v.x = to_tf32(ar[i].x); v.y = to_tf32(ar[i].y);
                v.z = to_tf32(ar[i].z); v.w = to_tf32(ar[i].w);
                *(float4*)(As + a_row[i] * ASTR + a_kc[i]) = v;
                *(float4*)(Bs + b_row[i] * BSTR + b_nc[i]) = br[i];
            }
            __syncthreads();
            buf ^= 1;
        }
    }

    // epilogue: + bias, float2 stores
#pragma unroll
    for (int mt = 0; mt < 4; mt++) {
        const int r = bM + warpM * 64 + mt * 16 + gid;
#pragma unroll
        for (int nt = 0; nt < 4; nt++) {
            const int c = bN + warpN * 32 + nt * 8 + tig * 2;
            const float2 bz = *(const float2*)(bias + c);
            float2 v0, v1;
            v0.x = acc[mt][nt][0] + bz.x;
            v0.y = acc[mt][nt][1] + bz.y;
            v1.x = acc[mt][nt][2] + bz.x;
            v1.y = acc[mt][nt][3] + bz.y;
            *(float2*)(out + (size_t)r * 4096 + c) = v0;
            *(float2*)(out + (size_t)(r + 8) * 4096 + c) = v1;
        }
    }
}

// ---------------------------------------------------------------------------
extern "C" void kernel_launch(void* const* d_in, const int* in_sizes, int n_in,
                              void* d_out, int out_size) {
    const float* x      = (const float*)d_in[0];
    const float* first  = (const float*)d_in[1];
    const float* middle = (const float*)d_in[2];
    const float* last   = (const float*)d_in[3];
    const float* bias   = (const float*)d_in[4];
    float* out = (float*)d_out;

    mpo_stage1<<<4096, 256>>>(first, middle);

    dim3 g2(4096, 16);
    mpo_stage2<<<g2, 256>>>(last);

    cudaFuncSetAttribute(mpo_gemm, cudaFuncAttributeMaxDynamicSharedMemorySize,
                         SMEM_BYTES);
    dim3 gg(32, 16);   // N-blocks x M-blocks
    mpo_gemm<<<gg, 256, SMEM_BYTES>>>(x, bias, out);
}

// round 4
// speedup vs baseline: 1.3876x; 1.3876x over previous
#include <cuda_runtime.h>
#include <cstdint>

// ---------------------------------------------------------------------------
// Scratch (__device__ globals — no allocations allowed)
// ---------------------------------------------------------------------------
static __device__ float g_T[16 * 16 * 16 * 16 * 16];   //  4 MB  T[i][j][m][n][s]
static __device__ float g_W[4096 * 4096];              // 64 MB  W[k=ijk][n=mno], tf32
static __device__ float g_Xt[2048 * 4096];             // 32 MB  X tf32-rounded

__device__ __forceinline__ float to_tf32(float x) {
    float y;
    asm("cvt.rna.tf32.f32 %0, %1;" : "=f"(y) : "f"(x));
    return y;
}

// ---------------------------------------------------------------------------
// Stage 1: T[i,j,m,n,s] = sum_r first[i,r,m] * middle[j,r,s,n]
// ---------------------------------------------------------------------------
__global__ void mpo_stage1(const float* __restrict__ first,
                           const float* __restrict__ middle) {
    __shared__ float F[256];     // first[i][r][m]
    __shared__ float Md[4096];   // middle[j][r][s][n]
    const int i = blockIdx.x >> 4, j = blockIdx.x & 15;
    const int t = threadIdx.x;
    F[t] = first[i * 256 + t];
#pragma unroll
    for (int q = 0; q < 16; q++) Md[t + q * 256] = middle[j * 4096 + t + q * 256];
    __syncthreads();
#pragma unroll
    for (int q = 0; q < 16; q++) {
        int z = t + q * 256;                 // z = m*256 + n*16 + s
        int m = z >> 8, n = (z >> 4) & 15, s = z & 15;
        float acc = 0.f;
#pragma unroll
        for (int r = 0; r < 16; r++)
            acc += F[r * 16 + m] * Md[r * 256 + s * 16 + n];
        g_T[(i * 16 + j) * 4096 + z] = acc;
    }
}

// ---------------------------------------------------------------------------
// Stage 2: W[(i,j,k), (m,n,o)] = sum_s T[i,j,m,n,s] * last[k,s,o]
// Row-major W (k rows, n cols). Block = (i,j); coalesced 1KB row-chunks.
// ---------------------------------------------------------------------------
__global__ void mpo_stage2(const float* __restrict__ last) {
    __shared__ float L[4096];    // last[k][s][o]
    __shared__ float T[4096];    // T[i,j][m][n][s]
    const int b = blockIdx.x;    // i*16 + j
    const int t = threadIdx.x;
#pragma unroll
    for (int q = 0; q < 16; q++) {
        L[t + q * 256] = last[t + q * 256];
        T[t + q * 256] = g_T[b * 4096 + t + q * 256];
    }
    __syncthreads();
    const int n = t >> 4, o = t & 15;
#pragma unroll 1
    for (int m = 0; m < 16; m++) {
        float Tm[16];
#pragma unroll
        for (int s = 0; s < 16; s++) Tm[s] = T[m * 256 + n * 16 + s];
#pragma unroll
        for (int k = 0; k < 16; k++) {
            float acc = 0.f;
#pragma unroll
            for (int s = 0; s < 16; s++) acc += Tm[s] * L[k * 256 + s * 16 + o];
            g_W[(size_t)(b * 16 + k) * 4096 + m * 256 + t] = to_tf32(acc);
        }
    }
}

// ---------------------------------------------------------------------------
// X -> tf32 (RNA) preconvert
// ---------------------------------------------------------------------------
__global__ void mpo_convx(const float* __restrict__ x) {
    int id = blockIdx.x * 256 + threadIdx.x;   // float4 index, 2,097,152 total
    float4 v = ((const float4*)x)[id];
    v.x = to_tf32(v.x); v.y = to_tf32(v.y); v.z = to_tf32(v.z); v.w = to_tf32(v.w);
    ((float4*)g_Xt)[id] = v;
}

// ---------------------------------------------------------------------------
// Stage 3: out(2048x4096) = Xt @ W + bias   (tf32 mma.sync, cp.async 3-stage)
// CTA 128x128, BK=32, 4 warps (warp tile 64x64), 2 CTAs/SM.
// A smem [m][36] (banks 4*gid+tig), B smem [k][136] (banks 8*tig+gid).
// ---------------------------------------------------------------------------
#define ASTR 36
#define BSTR 136
#define A_FL (128 * ASTR)            // 4608 floats
#define B_FL (32 * BSTR)             // 4352 floats
#define STG_FL (A_FL + B_FL)         // 8960 floats
#define STG_BYTES (STG_FL * 4)       // 35840
#define SMEM_BYTES (3 * STG_BYTES)   // 107520

__device__ __forceinline__ void cpa16(uint32_t saddr, const void* gaddr) {
    asm volatile("cp.async.cg.shared.global [%0], [%1], 16;"
                 :: "r"(saddr), "l"(gaddr));
}

__global__ void __launch_bounds__(128, 2)
mpo_gemm(const float* __restrict__ bias, float* __restrict__ out) {
    extern __shared__ float sm[];
    const int tid  = threadIdx.x;
    const int lane = tid & 31, wid = tid >> 5;
    const int gid  = lane >> 2, tig = lane & 3;
    const int warpM = wid & 1, warpN = wid >> 1;
    const int bM = blockIdx.y << 7;
    const int bN = blockIdx.x << 7;

    uint32_t smb;
    asm("{ .reg .u64 t; cvta.to.shared.u64 t, %1; cvt.u32.u64 %0, t; }"
        : "=r"(smb) : "l"(sm));

    float acc[4][8][4];
#pragma unroll
    for (int mt = 0; mt < 4; mt++)
#pragma unroll
        for (int nt = 0; nt < 8; nt++)
#pragma unroll
            for (int q = 0; q < 4; q++) acc[mt][nt][q] = 0.f;

    // cp.async issue: 8 A-chunks + 8 B-chunks per thread per k-tile
    auto issue = [&](int kt) {
        const uint32_t so = (uint32_t)(kt % 3) * STG_BYTES;
        const float* gA = g_Xt + kt * 32;
        const float* gB = g_W + (size_t)kt * 32 * 4096;
#pragma unroll
        for (int i = 0; i < 8; i++) {
            int z = tid + i * 128;
            int mr = z >> 3, kc = (z & 7) << 2;
            cpa16(smb + so + (uint32_t)(mr * ASTR + kc) * 4,
                  gA + (size_t)(bM + mr) * 4096 + kc);
        }
#pragma unroll
        for (int i = 0; i < 8; i++) {
            int z = tid + i * 128;
            int kr = z >> 5, nc = (z & 31) << 2;
            cpa16(smb + so + (uint32_t)(A_FL + kr * BSTR + nc) * 4,
                  gB + (size_t)kr * 4096 + bN + nc);
        }
    };

    issue(0);
    asm volatile("cp.async.commit_group;");
    issue(1);
    asm volatile("cp.async.commit_group;");

    const int aBase = (warpM * 64 + gid) * ASTR;
    const int bBase = warpN * 64 + gid;

    for (int kt = 0; kt < 128; kt++) {
        asm volatile("cp.async.wait_group 1;");
        __syncthreads();

        const float* As = sm + (kt % 3) * STG_FL;
        const float* Bs = As + A_FL;
#pragma unroll
        for (int ks = 0; ks < 4; ks++) {
            const int k0 = ks * 8 + tig;
            uint32_t b[8][2];
            const float* bp = Bs + k0 * BSTR + bBase;
#pragma unroll
            for (int nt = 0; nt < 8; nt++) {
                b[nt][0] = __float_as_uint(bp[nt * 8]);
                b[nt][1] = __float_as_uint(bp[nt * 8 + 4 * BSTR]);
            }
#pragma unroll
            for (int mt = 0; mt < 4; mt++) {
                const float* ap = As + aBase + mt * (16 * ASTR) + ks * 8 + tig;
                uint32_t a0 = __float_as_uint(ap[0]);
                uint32_t a1 = __float_as_uint(ap[8 * ASTR]);
                uint32_t a2 = __float_as_uint(ap[4]);
                uint32_t a3 = __float_as_uint(ap[8 * ASTR + 4]);
#pragma unroll
                for (int nt = 0; nt < 8; nt++) {
                    asm volatile(
                        "mma.sync.aligned.m16n8k8.row.col.f32.tf32.tf32.f32 "
                        "{%0,%1,%2,%3}, {%4,%5,%6,%7}, {%8,%9}, {%0,%1,%2,%3};\n"
                        : "+f"(acc[mt][nt][0]), "+f"(acc[mt][nt][1]),
                          "+f"(acc[mt][nt][2]), "+f"(acc[mt][nt][3])
                        : "r"(a0), "r"(a1), "r"(a2), "r"(a3),
                          "r"(b[nt][0]), "r"(b[nt][1]));
                }
            }
        }

        if (kt + 2 < 128) issue(kt + 2);
        asm volatile("cp.async.commit_group;");
    }

    // epilogue: + bias, float2 stores (4-thread 32B segments, sector-aligned)
#pragma unroll
    for (int mt = 0; mt < 4; mt++) {
        const int r = bM + warpM * 64 + mt * 16 + gid;
#pragma unroll
        for (int nt = 0; nt < 8; nt++) {
            const int c = bN + warpN * 64 + nt * 8 + tig * 2;
            const float2 bz = *(const float2*)(bias + c);
            float2 v0, v1;
            v0.x = acc[mt][nt][0] + bz.x;
            v0.y = acc[mt][nt][1] + bz.y;
            v1.x = acc[mt][nt][2] + bz.x;
            v1.y = acc[mt][nt][3] + bz.y;
            *(float2*)(out + (size_t)r * 4096 + c) = v0;
            *(float2*)(out + (size_t)(r + 8) * 4096 + c) = v1;
        }
    }
}

// ---------------------------------------------------------------------------
extern "C" void kernel_launch(void* const* d_in, const int* in_sizes, int n_in,
                              void* d_out, int out_size) {
    const float* x      = (const float*)d_in[0];
    const float* first  = (const float*)d_in[1];
    const float* middle = (const float*)d_in[2];
    const float* last   = (const float*)d_in[3];
    const float* bias   = (const float*)d_in[4];
    float* out = (float*)d_out;

    mpo_stage1<<<256, 256>>>(first, middle);
    mpo_stage2<<<256, 256>>>(last);
    mpo_convx<<<8192, 256>>>(x);

    cudaFuncSetAttribute(mpo_gemm, cudaFuncAttributeMaxDynamicSharedMemorySize,
                         SMEM_BYTES);
    dim3 gg(32, 16);   // 32 n-tiles x 16 m-tiles
    mpo_gemm<<<gg, 128, SMEM_BYTES>>>(bias, out);
}

// round 5
// speedup vs baseline: 2.6749x; 1.9277x over previous
#include <cuda_runtime.h>
#include <cuda_fp16.h>
#include <cstdint>

// ---------------------------------------------------------------------------
// Scratch (__device__ globals — no allocations allowed)
// ---------------------------------------------------------------------------
static __device__ float  g_T[16 * 16 * 16 * 16 * 16];   //  4 MB  T[i][j][m][n][s]
static __device__ __half g_Wh[4096 * 4096];             // 32 MB  Wh[n=mno][k=ijk], fp16 x1024
static __device__ __half g_Xh[2048 * 4096];             // 16 MB  X fp16

#define W_SCALE   1024.0f
#define INV_SCALE 0.0009765625f

// ---------------------------------------------------------------------------
// Stage 1: T[i,j,m,n,s] = sum_r first[i,r,m] * middle[j,r,s,n]   (fp32)
// ---------------------------------------------------------------------------
__global__ void mpo_stage1(const float* __restrict__ first,
                           const float* __restrict__ middle) {
    __shared__ float F[256];     // first[i][r][m]
    __shared__ float Md[4096];   // middle[j][r][s][n]
    const int i = blockIdx.x >> 4, j = blockIdx.x & 15;
    const int t = threadIdx.x;
    F[t] = first[i * 256 + t];
#pragma unroll
    for (int q = 0; q < 16; q++) Md[t + q * 256] = middle[j * 4096 + t + q * 256];
    __syncthreads();
#pragma unroll
    for (int q = 0; q < 16; q++) {
        int z = t + q * 256;                 // z = m*256 + n*16 + s
        int m = z >> 8, n = (z >> 4) & 15, s = z & 15;
        float acc = 0.f;
#pragma unroll
        for (int r = 0; r < 16; r++)
            acc += F[r * 16 + m] * Md[r * 256 + s * 16 + n];
        g_T[(i * 16 + j) * 4096 + z] = acc;
    }
}

// ---------------------------------------------------------------------------
// Stage 2: Wh[(m,n,o), (i,j,k)] = 1024 * sum_s T[i,j,m,n,s] * last[k,s,o]
// n-major (transposed) fp16 W. Block = (m,n); 256 threads = (i,j).
// Per o: thread t writes 16 contiguous halves (32B) at col t*16 — coalesced.
// ---------------------------------------------------------------------------
__global__ void mpo_stage2(const float* __restrict__ last) {
    __shared__ float L[4096];    // last[k][s][o]
    const int m = blockIdx.x >> 4, n = blockIdx.x & 15;
    const int t = threadIdx.x;   // t = i*16 + j
#pragma unroll
    for (int q = 0; q < 16; q++) L[t + q * 256] = last[t + q * 256];
    float Ts[16];
    const float* tp = g_T + (size_t)t * 4096 + m * 256 + n * 16;
#pragma unroll
    for (int s = 0; s < 16; s++) Ts[s] = tp[s];
    __syncthreads();
#pragma unroll 1
    for (int o = 0; o < 16; o++) {
        __half v[16];
#pragma unroll
        for (int k = 0; k < 16; k++) {
            float acc = 0.f;
#pragma unroll
            for (int s = 0; s < 16; s++) acc += Ts[s] * L[k * 256 + s * 16 + o];
            v[k] = __float2half_rn(acc * W_SCALE);
        }
        __half* wp = g_Wh + (size_t)(m * 256 + n * 16 + o) * 4096 + t * 16;
        *(uint4*)(wp)     = *(const uint4*)(v);
        *(uint4*)(wp + 8) = *(const uint4*)(v + 8);
    }
}

// ---------------------------------------------------------------------------
// X -> fp16
// ---------------------------------------------------------------------------
__global__ void mpo_convx(const float* __restrict__ x) {
    int id = blockIdx.x * 256 + threadIdx.x;   // float4 index, 2,097,152 total
    float4 v = ((const float4*)x)[id];
    __half2 lo = __floats2half2_rn(v.x, v.y);
    __half2 hi = __floats2half2_rn(v.z, v.w);
    uint2 p;
    p.x = *(uint32_t*)&lo;
    p.y = *(uint32_t*)&hi;
    ((uint2*)g_Xh)[id] = p;
}

// ---------------------------------------------------------------------------
// Stage 3: out(2048x4096) = (Xh @ Wh^T) * 2^-10 + bias
// fp16 m16n8k16 mma.sync, 4-stage cp.async, ldmatrix fragments.
// CTA 128x128, BK=32, 4 warps (warp tile 64x64), 2 CTAs/SM.
// A smem [m 128][k 32] halves stride 40; B smem [n 128][k 32] halves stride 40.
// (row step 80B = 20 banks -> 8-row ldmatrix phases hit 32 distinct banks)
// ---------------------------------------------------------------------------
#define HSTR 40
#define TILE_B (128 * HSTR * 2)        // 10240 B per operand tile
#define STG_B  (2 * TILE_B)            // 20480 B per stage
#define NSTAGE 4
#define SMEM_BYTES (NSTAGE * STG_B)    // 81920 B

__device__ __forceinline__ void cpa16(uint32_t saddr, const void* gaddr) {
    asm volatile("cp.async.cg.shared.global [%0], [%1], 16;"
                 :: "r"(saddr), "l"(gaddr));
}

__global__ void __launch_bounds__(128, 2)
mpo_gemm(const float* __restrict__ bias, float* __restrict__ out) {
    extern __shared__ char sm[];
    uint32_t smb;
    asm("{ .reg .u64 t; cvta.to.shared.u64 t, %1; cvt.u32.u64 %0, t; }"
        : "=r"(smb) : "l"(sm));
    const int tid  = threadIdx.x;
    const int lane = tid & 31, wid = tid >> 5;
    const int gid  = lane >> 2, tig = lane & 3;
    const int warpM = wid & 1, warpN = wid >> 1;   // 2M x 2N warps
    const int bM = blockIdx.y << 7;
    const int bN = blockIdx.x << 7;

    float acc[4][8][4];
#pragma unroll
    for (int mt = 0; mt < 4; mt++)
#pragma unroll
        for (int nt = 0; nt < 8; nt++)
#pragma unroll
            for (int q = 0; q < 4; q++) acc[mt][nt][q] = 0.f;

    // per-thread cp.async coordinates: 4 A-chunks + 4 B-chunks of 16B
    // z = tid + i*128: row = z>>2 (0..127), chunk = z&3 (16B units along k)
    // issue one k-tile
    auto issue = [&](int kt) {
        const uint32_t so = smb + (uint32_t)(kt & 3) * STG_B;
        const __half* gA = g_Xh + (size_t)bM * 4096 + kt * 32;
        const __half* gB = g_Wh + (size_t)bN * 4096 + kt * 32;
#pragma unroll
        for (int i = 0; i < 4; i++) {
            int z = tid + i * 128, r = z >> 2, c = z & 3;
            uint32_t off = (uint32_t)(r * HSTR + c * 8) * 2;
            cpa16(so + off, gA + (size_t)r * 4096 + c * 8);
            cpa16(so + TILE_B + off, gB + (size_t)r * 4096 + c * 8);
        }
    };

    issue(0); asm volatile("cp.async.commit_group;");
    issue(1); asm volatile("cp.async.commit_group;");
    issue(2); asm volatile("cp.async.commit_group;");

    // ldmatrix lane-address components (stage-invariant)
    // A x4 (per mt, ks): rows m = warpM*64+mt*16+(lane&15), kcol = ks*16+((lane>>4)<<3)
    const uint32_t aRow = warpM * 64 + (lane & 15);
    const uint32_t aKof = (lane >> 4) << 3;
    // B x4 (per g, ks): rows n = warpN*64+g*16+((lane>>4)<<3)+(lane&7),
    //                   kcol = ks*16+(((lane>>3)&1)<<3)
    const uint32_t bRow = warpN * 64 + ((lane >> 4) << 3) + (lane & 7);
    const uint32_t bKof = ((lane >> 3) & 1) << 3;

    for (int kt = 0; kt < 128; kt++) {
        asm volatile("cp.async.wait_group 2;");
        __syncthreads();

        const uint32_t sA = smb + (uint32_t)(kt & 3) * STG_B;
        const uint32_t sB = sA + TILE_B;
#pragma unroll
        for (int ks = 0; ks < 2; ks++) {
            uint32_t a[4][4], b[8][2];
#pragma unroll
            for (int mt = 0; mt < 4; mt++) {
                uint32_t ad = sA + ((aRow + mt * 16) * HSTR + ks * 16 + aKof) * 2;
                asm volatile(
                    "ldmatrix.sync.aligned.m8n8.x4.shared.b16 {%0,%1,%2,%3}, [%4];"
                    : "=r"(a[mt][0]), "=r"(a[mt][1]), "=r"(a[mt][2]), "=r"(a[mt][3])
                    : "r"(ad));
            }
#pragma unroll
            for (int g = 0; g < 4; g++) {
                uint32_t bd = sB + ((bRow + g * 16) * HSTR + ks * 16 + bKof) * 2;
                asm volatile(
                    "ldmatrix.sync.aligned.m8n8.x4.shared.b16 {%0,%1,%2,%3}, [%4];"
                    : "=r"(b[2 * g][0]), "=r"(b[2 * g][1]),
                      "=r"(b[2 * g + 1][0]), "=r"(b[2 * g + 1][1])
                    : "r"(bd));
            }
#pragma unroll
            for (int mt = 0; mt < 4; mt++)
#pragma unroll
                for (int nt = 0; nt < 8; nt++) {
                    asm volatile(
                        "mma.sync.aligned.m16n8k16.row.col.f32.f16.f16.f32 "
                        "{%0,%1,%2,%3}, {%4,%5,%6,%7}, {%8,%9}, {%0,%1,%2,%3};\n"
                        : "+f"(acc[mt][nt][0]), "+f"(acc[mt][nt][1]),
                          "+f"(acc[mt][nt][2]), "+f"(acc[mt][nt][3])
                        : "r"(a[mt][0]), "r"(a[mt][1]), "r"(a[mt][2]), "r"(a[mt][3]),
                          "r"(b[nt][0]), "r"(b[nt][1]));
                }
        }

        if (kt + 3 < 128) issue(kt + 3);
        asm volatile("cp.async.commit_group;");
    }

    // epilogue: un-scale, + bias, float2 stores
#pragma unroll
    for (int mt = 0; mt < 4; mt++) {
        const int r = bM + warpM * 64 + mt * 16 + gid;
#pragma unroll
        for (int nt = 0; nt < 8; nt++) {
            const int c = bN + warpN * 64 + nt * 8 + tig * 2;
            const float2 bz = *(const float2*)(bias + c);
            float2 v0, v1;
            v0.x = acc[mt][nt][0] * INV_SCALE + bz.x;
            v0.y = acc[mt][nt][1] * INV_SCALE + bz.y;
            v1.x = acc[mt][nt][2] * INV_SCALE + bz.x;
            v1.y = acc[mt][nt][3] * INV_SCALE + bz.y;
            *(float2*)(out + (size_t)r * 4096 + c) = v0;
            *(float2*)(out + (size_t)(r + 8) * 4096 + c) = v1;
        }
    }
}

// ---------------------------------------------------------------------------
extern "C" void kernel_launch(void* const* d_in, const int* in_sizes, int n_in,
                              void* d_out, int out_size) {
    const float* x      = (const float*)d_in[0];
    const float* first  = (const float*)d_in[1];
    const float* middle = (const float*)d_in[2];
    const float* last   = (const float*)d_in[3];
    const float* bias   = (const float*)d_in[4];
    float* out = (float*)d_out;

    mpo_stage1<<<256, 256>>>(first, middle);
    mpo_stage2<<<256, 256>>>(last);
    mpo_convx<<<8192, 256>>>(x);

    cudaFuncSetAttribute(mpo_gemm, cudaFuncAttributeMaxDynamicSharedMemorySize,
                         SMEM_BYTES);
    dim3 gg(32, 16);   // 32 n-tiles x 16 m-tiles
    mpo_gemm<<<gg, 128, SMEM_BYTES>>>(bias, out);
}